// round 3
// baseline (speedup 1.0000x reference)
#include <cuda_runtime.h>
#include <cstdint>

#define B_    128
#define T_    1024
#define RNN_  1024
#define EMB_  512
#define ATT_  128
#define NF_   32
#define KS_   31
#define PAD_  15
#define ETILE_ 128
#define ENT_   (T_ / ETILE_)   // 8
#define CTILE_ 64
#define CNT_   (T_ / CTILE_)   // 16
#define CONVS_ 132             // padded s_conv row stride (floats)

typedef unsigned long long ull;

// dynamic smem layout (bytes) for energies kernel
#define OFF_WLOC2  0                        // 4096 ull  = 32768 B
#define OFF_WCONV2 32768                    // 1984 ull  = 15872 B
#define OFF_CONV   (32768 + 15872)          // 4224 f    = 16896 B
#define OFF_AW     (OFF_CONV + 16896)       // 320 f     = 1280 B
#define OFF_AWB    (OFF_AW + 1280)          // 320 f     = 1280 B
#define OFF_PQ     (OFF_AWB + 1280)         // 128 f     = 512 B
#define OFF_V2     (OFF_PQ + 512)           // 128 ull   = 1024 B
#define ESMEM_     (OFF_V2 + 1024)          // 69632 B

// ---------------- scratch (no allocations allowed) ----------------
__device__ float g_pq[B_ * ATT_];
__device__ float g_energies[B_ * T_];
__device__ float g_partial[B_ * CNT_ * EMB_];

// ---------------- helpers ----------------
__device__ __forceinline__ float tanh_fast(float x) {
    float y; asm("tanh.approx.f32 %0, %1;" : "=f"(y) : "f"(x)); return y;
}
__device__ __forceinline__ ull ffma2(ull a, ull b, ull c) {
    ull d; asm("fma.rn.f32x2 %0, %1, %2, %3;" : "=l"(d) : "l"(a), "l"(b), "l"(c));
    return d;
}
__device__ __forceinline__ ull add2(ull a, ull b) {
    ull d; asm("add.rn.f32x2 %0, %1, %2;" : "=l"(d) : "l"(a), "l"(b));
    return d;
}
__device__ __forceinline__ ull pack2(float lo, float hi) {
    ull d; asm("mov.b64 %0, {%1, %2};" : "=l"(d) : "f"(lo), "f"(hi)); return d;
}
__device__ __forceinline__ float2 unpack2(ull v) {
    float2 r; asm("mov.b64 {%0, %1}, %2;" : "=f"(r.x), "=f"(r.y) : "l"(v)); return r;
}

// ================= K1: pq[b,a] = hidden[b,:] @ w_query[:,a] =================
__global__ void pq_kernel(const float* __restrict__ hidden,
                          const float* __restrict__ wq) {
    __shared__ float s_h[RNN_];
    int b = blockIdx.x;
    int a = threadIdx.x;          // 128 threads
    const float* hrow = hidden + (size_t)b * RNN_;
    #pragma unroll
    for (int r = 0; r < RNN_ / 128; ++r) s_h[a + r * 128] = hrow[a + r * 128];
    __syncthreads();

    float acc = 0.f;
    #pragma unroll 16
    for (int k = 0; k < RNN_; ++k)
        acc = fmaf(s_h[k], wq[(size_t)k * ATT_ + a], acc);
    g_pq[b * ATT_ + a] = acc;
}

// ============ K2: fused conv -> loc -> tanh -> energies (t-packed f32x2) ============
// grid (ENT_, B_), 256 threads, dynamic smem ESMEM_
__global__ __launch_bounds__(256, 2) void energies_kernel(
    const float* __restrict__ aw,          // [B,2,T]
    const float* __restrict__ pmem,        // [B,T,ATT]
    const float* __restrict__ wconv,       // [NF,2,KS]
    const float* __restrict__ wloc,        // [NF,ATT]
    const float* __restrict__ vvec)        // [ATT]
{
    extern __shared__ __align__(16) char smem[];
    ull*   s_wloc2  = (ull*)(smem + OFF_WLOC2);     // [f][a] {w,w}
    ull*   s_wconv2 = (ull*)(smem + OFF_WCONV2);    // [f][ch*31+k] {w,w}
    float* s_conv   = (float*)(smem + OFF_CONV);    // [f][CONVS_]
    float* s_aw     = (float*)(smem + OFF_AW);      // [ch][160]
    float* s_awB    = (float*)(smem + OFF_AWB);     // shifted +1
    float* s_pq     = (float*)(smem + OFF_PQ);
    ull*   s_v2     = (ull*)(smem + OFF_V2);        // {v,v}

    const int b   = blockIdx.y;
    const int t0g = blockIdx.x * ETILE_;
    const int tid = threadIdx.x;

    // ---- stage shared ----
    for (int idx = tid; idx < NF_ * ATT_; idx += 256) {
        float w = wloc[idx]; s_wloc2[idx] = pack2(w, w);
    }
    for (int idx = tid; idx < NF_ * 2 * KS_; idx += 256) {
        float w = wconv[idx]; s_wconv2[idx] = pack2(w, w);
    }
    for (int idx = tid; idx < 2 * 160; idx += 256) {
        int ch = idx / 160, j = idx % 160;
        int gt  = t0g + j - PAD_;
        int gt2 = gt + 1;
        const float* row = aw + ((size_t)b * 2 + ch) * T_;
        s_aw [idx] = (gt  >= 0 && gt  < T_) ? row[gt]  : 0.f;
        s_awB[idx] = (gt2 >= 0 && gt2 < T_) ? row[gt2] : 0.f;
    }
    if (tid < ATT_) {
        s_pq[tid] = g_pq[b * ATT_ + tid];
        float vv = vvec[tid];
        s_v2[tid] = pack2(vv, vv);
    }
    __syncthreads();

    // ---- conv: thread = (filter f, 16 t), two 8-t halves to cap registers ----
    {
        const int f  = tid >> 3;          // 0..31
        const int tb = (tid & 7) * 16;    // 0..112
        ull acc2[8];
        #pragma unroll
        for (int i = 0; i < 8; ++i) acc2[i] = 0ull;

        const ull* wc2 = s_wconv2 + f * (2 * KS_);
        #pragma unroll
        for (int ch = 0; ch < 2; ++ch) {
            const float* awp  = s_aw  + ch * 160;
            const float* awbp = s_awB + ch * 160;
            #pragma unroll
            for (int h = 0; h < 2; ++h) {
                const int t0 = tb + 8 * h;
                ull we[19], wo[18];
                #pragma unroll
                for (int m = 0; m < 19; ++m) we[m] = *(const ull*)(awp  + t0 + 2 * m);
                #pragma unroll
                for (int m = 0; m < 18; ++m) wo[m] = *(const ull*)(awbp + t0 + 2 * m);
                #pragma unroll
                for (int k = 0; k < KS_; ++k) {
                    ull wk = wc2[ch * KS_ + k];
                    if ((k & 1) == 0) {
                        #pragma unroll
                        for (int j = 0; j < 4; ++j)
                            acc2[4*h + j] = ffma2(wk, we[j + (k >> 1)], acc2[4*h + j]);
                    } else {
                        #pragma unroll
                        for (int j = 0; j < 4; ++j)
                            acc2[4*h + j] = ffma2(wk, wo[j + ((k - 1) >> 1)], acc2[4*h + j]);
                    }
                }
            }
        }
        #pragma unroll
        for (int i = 0; i < 8; ++i)
            *(ull*)&s_conv[f * CONVS_ + tb + 2 * i] = acc2[i];
    }
    __syncthreads();

    // ---- loc + tanh + energies: warp = 16 t (8 t-pairs), lane = a-quad ----
    {
        const int w = tid >> 5, l = tid & 31;
        const int tloc = w * 16;
        const float4 pq4 = ((const float4*)s_pq)[l];
        const float4* pmem4 = (const float4*)pmem;
        const size_t gbase = ((size_t)b * T_ + t0g + tloc) * (ATT_ / 4) + l;

        ull accA[4][8];   // [a_local][t-pair], each = {val(t0), val(t1)}
        #pragma unroll
        for (int tp = 0; tp < 8; ++tp) {
            float4 p0 = pmem4[gbase + (size_t)(2 * tp)     * (ATT_ / 4)];
            float4 p1 = pmem4[gbase + (size_t)(2 * tp + 1) * (ATT_ / 4)];
            accA[0][tp] = pack2(p0.x + pq4.x, p1.x + pq4.x);
            accA[1][tp] = pack2(p0.y + pq4.y, p1.y + pq4.y);
            accA[2][tp] = pack2(p0.z + pq4.z, p1.z + pq4.z);
            accA[3][tp] = pack2(p0.w + pq4.w, p1.w + pq4.w);
        }

        #pragma unroll 4
        for (int f = 0; f < NF_; ++f) {
            const ulonglong2* wlp = (const ulonglong2*)(s_wloc2 + f * ATT_ + 4 * l);
            ulonglong2 wl01 = wlp[0];   // {wl[4l],wl[4l]}, {wl[4l+1],wl[4l+1]}
            ulonglong2 wl23 = wlp[1];
            const ulonglong2* cp2 = (const ulonglong2*)(s_conv + f * CONVS_ + tloc);
            ulonglong2 c01 = cp2[0], c23 = cp2[1], c45 = cp2[2], c67 = cp2[3];
            ull cp[8] = {c01.x, c01.y, c23.x, c23.y, c45.x, c45.y, c67.x, c67.y};
            #pragma unroll
            for (int tp = 0; tp < 8; ++tp) {
                accA[0][tp] = ffma2(cp[tp], wl01.x, accA[0][tp]);
                accA[1][tp] = ffma2(cp[tp], wl01.y, accA[1][tp]);
                accA[2][tp] = ffma2(cp[tp], wl23.x, accA[2][tp]);
                accA[3][tp] = ffma2(cp[tp], wl23.y, accA[3][tp]);
            }
        }

        const ulonglong2* vvp = (const ulonglong2*)(s_v2 + 4 * l);
        ulonglong2 vv01 = vvp[0], vv23 = vvp[1];
        #pragma unroll
        for (int tp = 0; tp < 8; ++tp) {
            float2 p0 = unpack2(accA[0][tp]);
            float2 p1 = unpack2(accA[1][tp]);
            float2 p2 = unpack2(accA[2][tp]);
            float2 p3 = unpack2(accA[3][tp]);
            ull e2 = 0ull;
            e2 = ffma2(vv01.x, pack2(tanh_fast(p0.x), tanh_fast(p0.y)), e2);
            e2 = ffma2(vv01.y, pack2(tanh_fast(p1.x), tanh_fast(p1.y)), e2);
            e2 = ffma2(vv23.x, pack2(tanh_fast(p2.x), tanh_fast(p2.y)), e2);
            e2 = ffma2(vv23.y, pack2(tanh_fast(p3.x), tanh_fast(p3.y)), e2);
            #pragma unroll
            for (int o = 16; o; o >>= 1)
                e2 = add2(e2, __shfl_xor_sync(0xffffffffu, e2, o));
            if (l == 0) {
                float2 ef = unpack2(e2);
                *(float2*)&g_energies[(size_t)b * T_ + t0g + tloc + 2 * tp] = ef;
            }
        }
    }
}

// ================= K3: softmax over T per row, write weights =================
__global__ __launch_bounds__(1024) void softmax_kernel(
    const unsigned char* __restrict__ mask,
    float* __restrict__ out_w)
{
    __shared__ float s_red[32];
    const int b = blockIdx.x, t = threadIdx.x;
    const int w = t >> 5, l = t & 31;

    float e = g_energies[(size_t)b * T_ + t];
    if (mask[(size_t)b * T_ + t]) e = -__int_as_float(0x7f800000);

    float m = e;
    #pragma unroll
    for (int o = 16; o; o >>= 1) m = fmaxf(m, __shfl_xor_sync(0xffffffffu, m, o));
    if (l == 0) s_red[w] = m;
    __syncthreads();
    if (w == 0) {
        float mm = s_red[l];
        #pragma unroll
        for (int o = 16; o; o >>= 1) mm = fmaxf(mm, __shfl_xor_sync(0xffffffffu, mm, o));
        if (l == 0) s_red[0] = mm;
    }
    __syncthreads();
    m = s_red[0];
    __syncthreads();

    float p = expf(e - m);
    float s = p;
    #pragma unroll
    for (int o = 16; o; o >>= 1) s += __shfl_xor_sync(0xffffffffu, s, o);
    if (l == 0) s_red[w] = s;
    __syncthreads();
    if (w == 0) {
        float ss = s_red[l];
        #pragma unroll
        for (int o = 16; o; o >>= 1) ss += __shfl_xor_sync(0xffffffffu, ss, o);
        if (l == 0) s_red[0] = ss;
    }
    __syncthreads();
    s = s_red[0];

    out_w[(size_t)b * T_ + t] = p / s;
}

// ============ K4: context partials: grid (CNT_, B_), 128 thr ============
__global__ __launch_bounds__(128) void context_partial_kernel(
    const float* __restrict__ memory,
    const float* __restrict__ out_w)
{
    const int c = blockIdx.x, b = blockIdx.y, d4 = threadIdx.x;
    __shared__ float s_w[CTILE_];
    if (threadIdx.x < CTILE_)
        s_w[threadIdx.x] = out_w[(size_t)b * T_ + c * CTILE_ + threadIdx.x];
    __syncthreads();

    const float4* mem4 = (const float4*)memory + ((size_t)b * T_ + c * CTILE_) * (EMB_ / 4) + d4;
    float4 acc = make_float4(0.f, 0.f, 0.f, 0.f);
    #pragma unroll 8
    for (int j = 0; j < CTILE_; ++j) {
        float wt = s_w[j];
        float4 mv = mem4[(size_t)j * (EMB_ / 4)];
        acc.x = fmaf(wt, mv.x, acc.x);
        acc.y = fmaf(wt, mv.y, acc.y);
        acc.z = fmaf(wt, mv.z, acc.z);
        acc.w = fmaf(wt, mv.w, acc.w);
    }
    ((float4*)g_partial)[((size_t)b * CNT_ + c) * (EMB_ / 4) + d4] = acc;
}

// ================= K5: reduce partials -> context =================
__global__ __launch_bounds__(128) void context_reduce_kernel(float* __restrict__ out) {
    const int b = blockIdx.x, d4 = threadIdx.x;
    const float4* p4 = (const float4*)g_partial;
    float4 s = make_float4(0.f, 0.f, 0.f, 0.f);
    #pragma unroll
    for (int c = 0; c < CNT_; ++c) {
        float4 v = p4[((size_t)b * CNT_ + c) * (EMB_ / 4) + d4];
        s.x += v.x; s.y += v.y; s.z += v.z; s.w += v.w;
    }
    ((float4*)out)[(size_t)b * (EMB_ / 4) + d4] = s;
}

// ============================ launch ============================
extern "C" void kernel_launch(void* const* d_in, const int* in_sizes, int n_in,
                              void* d_out, int out_size) {
    const float* hidden = (const float*)d_in[0];
    const float* memory = (const float*)d_in[1];
    const float* pmem   = (const float*)d_in[2];
    const float* awcat  = (const float*)d_in[3];
    const unsigned char* mask = (const unsigned char*)d_in[4];
    const float* wq     = (const float*)d_in[5];
    const float* wconv  = (const float*)d_in[6];
    const float* wloc   = (const float*)d_in[7];
    const float* vvec   = (const float*)d_in[8];

    float* out   = (float*)d_out;
    float* out_w = out + (size_t)B_ * EMB_;

    cudaFuncSetAttribute(energies_kernel,
                         cudaFuncAttributeMaxDynamicSharedMemorySize, ESMEM_);

    pq_kernel<<<B_, 128>>>(hidden, wq);
    energies_kernel<<<dim3(ENT_, B_), 256, ESMEM_>>>(awcat, pmem, wconv, wloc, vvec);
    softmax_kernel<<<B_, T_>>>(mask, out_w);
    context_partial_kernel<<<dim3(CNT_, B_), 128>>>(memory, out_w);
    context_reduce_kernel<<<B_, 128>>>(out);
}

// round 5
// speedup vs baseline: 1.1418x; 1.1418x over previous
#include <cuda_runtime.h>
#include <cuda_bf16.h>
#include <cstdint>

#define B_    128
#define T_    1024
#define RNN_  1024
#define EMB_  512
#define ATT_  128
#define NF_   32
#define KS_   31
#define PAD_  15
#define CTILE_ 64
#define CNT_   (T_ / CTILE_)   // 16

// energies GEMM: D[128 t, 128 a] = A[t, 192] * B[192, a]
// segments: s0: Ahi*Bhi, s1: Alo*Bhi, s2: Ahi*Blo   (k=64 each, j=0..61 data, 62=pq row, 63=pad)
#define LDAB_  136             // smem row stride in bf16 elems (272 B, 16B mult, conflict-free)
#define OFF_B_    (128 * LDAB_ * 2)            // 34816: B after A
#define OFF_V_    (OFF_B_ + 192 * LDAB_ * 2)   // 87040: v (128 f)
#define OFF_AW_   (OFF_V_ + 512)               // 87552: aw window 2x160 f
#define ESMEM_    (OFF_AW_ + 1280)             // 88832

// ---------------- scratch (no allocations allowed) ----------------
__device__ float g_pq[B_ * ATT_];
__device__ float g_energies[B_ * T_];
__device__ float g_partial[B_ * CNT_ * EMB_];
__device__ __nv_bfloat16 g_W2bf[192 * 128];   // B operand rows: [hi | hi dup | lo], pq rows zero

// ---------------- helpers ----------------
__device__ __forceinline__ float tanh_fast(float x) {
    float y; asm("tanh.approx.f32 %0, %1;" : "=f"(y) : "f"(x)); return y;
}
__device__ __forceinline__ uint32_t smem_u32(const void* p) {
    uint32_t a;
    asm("{ .reg .u64 t; cvta.to.shared.u64 t, %1; cvt.u32.u64 %0, t; }" : "=r"(a) : "l"(p));
    return a;
}
__device__ __forceinline__ void ldsm_x4(uint32_t* r, uint32_t addr) {
    asm volatile("ldmatrix.sync.aligned.m8n8.x4.shared.b16 {%0,%1,%2,%3}, [%4];"
                 : "=r"(r[0]), "=r"(r[1]), "=r"(r[2]), "=r"(r[3]) : "r"(addr));
}
__device__ __forceinline__ void ldsm_x2t(uint32_t& b0, uint32_t& b1, uint32_t addr) {
    asm volatile("ldmatrix.sync.aligned.m8n8.x2.trans.shared.b16 {%0,%1}, [%2];"
                 : "=r"(b0), "=r"(b1) : "r"(addr));
}
__device__ __forceinline__ void mma_bf16(float* d, const uint32_t* a, uint32_t b0, uint32_t b1) {
    asm volatile("mma.sync.aligned.m16n8k16.row.col.f32.bf16.bf16.f32 "
                 "{%0,%1,%2,%3}, {%4,%5,%6,%7}, {%8,%9}, {%0,%1,%2,%3};"
                 : "+f"(d[0]), "+f"(d[1]), "+f"(d[2]), "+f"(d[3])
                 : "r"(a[0]), "r"(a[1]), "r"(a[2]), "r"(a[3]), "r"(b0), "r"(b1));
}

// ================= K1: prep — pq tiles (blocks 0..63) + W2 build (block 64) =================
__global__ __launch_bounds__(256) void prep_kernel(
    const float* __restrict__ hidden, const float* __restrict__ wq,
    const float* __restrict__ wconv,  const float* __restrict__ wloc)
{
    __shared__ float s_buf[8192];
    const int tid = threadIdx.x;

    if (blockIdx.x < 64) {
        const int b0 = (blockIdx.x >> 3) * 16;
        const int a0 = (blockIdx.x & 7) * 16;
        float* sH = s_buf;              // [16][129]
        float* sW = s_buf + 16 * 129;   // [128][17]
        const int bb = tid >> 4, ag = tid & 15;
        float acc0 = 0.f, acc1 = 0.f;
        for (int kc = 0; kc < RNN_; kc += 128) {
            __syncthreads();
            #pragma unroll
            for (int i = 0; i < 8; ++i) {
                int m = tid + 256 * i, r = m >> 7, c = m & 127;
                sH[r * 129 + c] = hidden[(size_t)(b0 + r) * RNN_ + kc + c];
            }
            #pragma unroll
            for (int i = 0; i < 8; ++i) {
                int m = tid + 256 * i, r = m >> 4, c = m & 15;
                sW[r * 17 + c] = wq[(size_t)(kc + r) * ATT_ + a0 + c];
            }
            __syncthreads();
            #pragma unroll
            for (int k = 0; k < 128; k += 2) {
                acc0 = fmaf(sH[bb * 129 + k],     sW[k * 17 + ag],       acc0);
                acc1 = fmaf(sH[bb * 129 + k + 1], sW[(k + 1) * 17 + ag], acc1);
            }
        }
        g_pq[(b0 + bb) * ATT_ + a0 + ag] = acc0 + acc1;
    } else {
        // W2[j,a] = sum_f wconv[f*62+j] * wloc[f*128+a], j in [0,62)
        float* s_W2 = s_buf;   // [62*128]
        for (int m = tid; m < 62 * 128; m += 256) {
            int j = m >> 7, a = m & 127;
            float acc = 0.f;
            #pragma unroll 8
            for (int f = 0; f < NF_; ++f)
                acc = fmaf(wconv[f * 62 + j], wloc[f * ATT_ + a], acc);
            s_W2[m] = acc;
        }
        __syncthreads();
        for (int m = tid; m < 192 * 128; m += 256) {
            int row = m >> 7, a = m & 127;
            int seg = row >> 6, j = row & 63;
            __nv_bfloat16 out = __float2bfloat16_rn(0.f);
            if (j < 62) {
                float w = s_W2[j * 128 + a];
                __nv_bfloat16 hi = __float2bfloat16_rn(w);
                out = (seg < 2) ? hi : __float2bfloat16_rn(w - __bfloat162float(hi));
            }
            g_W2bf[m] = out;
        }
    }
}

// ============ K2: energies via mma.sync bf16 + fused epilogue ============
// grid (8, B_), 256 threads (8 warps), dynamic smem ESMEM_
__global__ __launch_bounds__(256, 2) void energies_kernel(
    const float* __restrict__ aw,      // [B,2,T]
    const float* __restrict__ pmem,    // [B,T,ATT]
    const float* __restrict__ vvec)    // [ATT]
{
    extern __shared__ __align__(16) char sm[];
    const uint32_t sbase = smem_u32(sm);

    const int b   = blockIdx.y;
    const int t0g = blockIdx.x * 128;
    const int tid = threadIdx.x;
    const int wm  = tid >> 5, lane = tid & 31;

    float* s_v  = (float*)(sm + OFF_V_);
    float* s_aw = (float*)(sm + OFF_AW_);

    // ---- stage: aw window, v, B copy (W2 bf16, rows plain stride->padded) ----
    for (int idx = tid; idx < 320; idx += 256) {
        int ch = idx / 160, jj = idx % 160;
        int gt = t0g + jj - PAD_;
        s_aw[idx] = (gt >= 0 && gt < T_) ? aw[((size_t)b * 2 + ch) * T_ + gt] : 0.f;
    }
    if (tid < 128) s_v[tid] = vvec[tid];
    {
        const uint32_t* gw = (const uint32_t*)g_W2bf;   // [192][64] u32
        for (int m = tid; m < 192 * 64; m += 256) {
            int r = m >> 6, c = m & 63;
            *(uint32_t*)(sm + OFF_B_ + r * (LDAB_ * 2) + c * 4) = gw[m];
        }
    }
    __syncthreads();

    // ---- build A rows (hi cols 0..63, lo cols 64..127) + pq rows in B ----
    {
        const int row = tid >> 1, jh = tid & 1;
        __nv_bfloat16* arow = (__nv_bfloat16*)(sm + row * (LDAB_ * 2));
        #pragma unroll
        for (int q = 0; q < 31; ++q) {
            int j = jh * 31 + q;
            int ch = j >> 5 | ((j >> 4) & (j >> 0) & 0); // placeholder, computed below
            (void)ch;
            float x = (j < 31) ? s_aw[row + j] : s_aw[160 + row + (j - 31)];
            __nv_bfloat16 hi = __float2bfloat16_rn(x);
            arow[j]      = hi;
            arow[64 + j] = __float2bfloat16_rn(x - __bfloat162float(hi));
        }
        if (jh == 0) {
            arow[62]  = __float2bfloat16_rn(1.f);   // pq row multiplier
            arow[63]  = __float2bfloat16_rn(0.f);
            arow[126] = __float2bfloat16_rn(0.f);   // lo of 1.0
            arow[127] = __float2bfloat16_rn(0.f);
        }
    }
    if (tid < 128) {
        float q = g_pq[b * ATT_ + tid];
        __nv_bfloat16 hi = __float2bfloat16_rn(q);
        __nv_bfloat16 lo = __float2bfloat16_rn(q - __bfloat162float(hi));
        __nv_bfloat16* sB = (__nv_bfloat16*)(sm + OFF_B_);
        sB[ 62 * LDAB_ + tid] = hi;
        sB[126 * LDAB_ + tid] = hi;
        sB[190 * LDAB_ + tid] = lo;
    }
    __syncthreads();

    // ---- MMA mainloop: warp wm = t rows [16wm,16wm+16), 16 n-tiles, 12 k-steps ----
    float acc[16][4];
    #pragma unroll
    for (int n = 0; n < 16; ++n) {
        acc[n][0] = 0.f; acc[n][1] = 0.f; acc[n][2] = 0.f; acc[n][3] = 0.f;
    }
    const uint32_t aRowAddr = sbase + (16 * wm + (lane & 15)) * (LDAB_ * 2) + (lane >> 4) * 16;
    const uint32_t bRowAddr = sbase + OFF_B_ + (lane & 15) * (LDAB_ * 2);

    #pragma unroll
    for (int s = 0; s < 12; ++s) {
        const int ks = (s < 8) ? s : (s - 8);      // A seg2 reuses Ahi storage
        uint32_t af[4];
        ldsm_x4(af, aRowAddr + ks * 32);           // 16 bf16 cols = 32 B
        const uint32_t bS = bRowAddr + s * 16 * (LDAB_ * 2);
        #pragma unroll
        for (int n = 0; n < 16; ++n) {
            uint32_t b0, b1;
            ldsm_x2t(b0, b1, bS + n * 16);         // 8 bf16 cols = 16 B
            mma_bf16(acc[n], af, b0, b1);
        }
    }

    // ---- epilogue: e[t] = sum_a tanh(D + pmem) * v ----
    {
        const int r   = lane >> 2;                 // row within 16-row slab
        const int cq  = (lane & 3) * 2;
        const int tA  = t0g + 16 * wm + r;
        const float* pmA = pmem + ((size_t)b * T_ + tA) * ATT_;
        const float* pmB = pmA + 8 * ATT_;
        float eA = 0.f, eB = 0.f;
        #pragma unroll
        for (int n = 0; n < 16; ++n) {
            const int col = 8 * n + cq;
            float2 v2 = *(const float2*)(s_v + col);
            float2 pa = *(const float2*)(pmA + col);
            float2 pb = *(const float2*)(pmB + col);
            eA = fmaf(tanh_fast(acc[n][0] + pa.x), v2.x, eA);
            eA = fmaf(tanh_fast(acc[n][1] + pa.y), v2.y, eA);
            eB = fmaf(tanh_fast(acc[n][2] + pb.x), v2.x, eB);
            eB = fmaf(tanh_fast(acc[n][3] + pb.y), v2.y, eB);
        }
        eA += __shfl_xor_sync(0xffffffffu, eA, 1);
        eA += __shfl_xor_sync(0xffffffffu, eA, 2);
        eB += __shfl_xor_sync(0xffffffffu, eB, 1);
        eB += __shfl_xor_sync(0xffffffffu, eB, 2);
        if ((lane & 3) == 0) {
            g_energies[(size_t)b * T_ + tA]     = eA;
            g_energies[(size_t)b * T_ + tA + 8] = eB;
        }
    }
}

// ================= K3: softmax over T per row, write weights =================
__global__ __launch_bounds__(1024) void softmax_kernel(
    const unsigned char* __restrict__ mask,
    float* __restrict__ out_w)
{
    __shared__ float s_red[32];
    const int b = blockIdx.x, t = threadIdx.x;
    const int w = t >> 5, l = t & 31;

    float e = g_energies[(size_t)b * T_ + t];
    if (mask[(size_t)b * T_ + t]) e = -__int_as_float(0x7f800000);

    float m = e;
    #pragma unroll
    for (int o = 16; o; o >>= 1) m = fmaxf(m, __shfl_xor_sync(0xffffffffu, m, o));
    if (l == 0) s_red[w] = m;
    __syncthreads();
    if (w == 0) {
        float mm = s_red[l];
        #pragma unroll
        for (int o = 16; o; o >>= 1) mm = fmaxf(mm, __shfl_xor_sync(0xffffffffu, mm, o));
        if (l == 0) s_red[0] = mm;
    }
    __syncthreads();
    m = s_red[0];
    __syncthreads();

    float p = expf(e - m);
    float s = p;
    #pragma unroll
    for (int o = 16; o; o >>= 1) s += __shfl_xor_sync(0xffffffffu, s, o);
    if (l == 0) s_red[w] = s;
    __syncthreads();
    if (w == 0) {
        float ss = s_red[l];
        #pragma unroll
        for (int o = 16; o; o >>= 1) ss += __shfl_xor_sync(0xffffffffu, ss, o);
        if (l == 0) s_red[0] = ss;
    }
    __syncthreads();
    s = s_red[0];

    out_w[(size_t)b * T_ + t] = p / s;
}

// ============ K4: context partials: grid (CNT_, B_), 128 thr ============
__global__ __launch_bounds__(128) void context_partial_kernel(
    const float* __restrict__ memory,
    const float* __restrict__ out_w)
{
    const int c = blockIdx.x, b = blockIdx.y, d4 = threadIdx.x;
    __shared__ float s_w[CTILE_];
    if (threadIdx.x < CTILE_)
        s_w[threadIdx.x] = out_w[(size_t)b * T_ + c * CTILE_ + threadIdx.x];
    __syncthreads();

    const float4* mem4 = (const float4*)memory + ((size_t)b * T_ + c * CTILE_) * (EMB_ / 4) + d4;
    float4 acc = make_float4(0.f, 0.f, 0.f, 0.f);
    #pragma unroll 8
    for (int j = 0; j < CTILE_; ++j) {
        float wt = s_w[j];
        float4 mv = mem4[(size_t)j * (EMB_ / 4)];
        acc.x = fmaf(wt, mv.x, acc.x);
        acc.y = fmaf(wt, mv.y, acc.y);
        acc.z = fmaf(wt, mv.z, acc.z);
        acc.w = fmaf(wt, mv.w, acc.w);
    }
    ((float4*)g_partial)[((size_t)b * CNT_ + c) * (EMB_ / 4) + d4] = acc;
}

// ================= K5: reduce partials -> context =================
__global__ __launch_bounds__(128) void context_reduce_kernel(float* __restrict__ out) {
    const int b = blockIdx.x, d4 = threadIdx.x;
    const float4* p4 = (const float4*)g_partial;
    float4 s = make_float4(0.f, 0.f, 0.f, 0.f);
    #pragma unroll
    for (int c = 0; c < CNT_; ++c) {
        float4 v = p4[((size_t)b * CNT_ + c) * (EMB_ / 4) + d4];
        s.x += v.x; s.y += v.y; s.z += v.z; s.w += v.w;
    }
    ((float4*)out)[(size_t)b * (EMB_ / 4) + d4] = s;
}

// ============================ launch ============================
extern "C" void kernel_launch(void* const* d_in, const int* in_sizes, int n_in,
                              void* d_out, int out_size) {
    const float* hidden = (const float*)d_in[0];
    const float* memory = (const float*)d_in[1];
    const float* pmem   = (const float*)d_in[2];
    const float* awcat  = (const float*)d_in[3];
    const unsigned char* mask = (const unsigned char*)d_in[4];
    const float* wq     = (const float*)d_in[5];
    const float* wconv  = (const float*)d_in[6];
    const float* wloc   = (const float*)d_in[7];
    const float* vvec   = (const float*)d_in[8];

    float* out   = (float*)d_out;
    float* out_w = out + (size_t)B_ * EMB_;

    cudaFuncSetAttribute(energies_kernel,
                         cudaFuncAttributeMaxDynamicSharedMemorySize, ESMEM_);

    prep_kernel<<<65, 256>>>(hidden, wq, wconv, wloc);
    energies_kernel<<<dim3(8, B_), 256, ESMEM_>>>(awcat, pmem, vvec);
    softmax_kernel<<<B_, T_>>>(mask, out_w);
    context_partial_kernel<<<dim3(CNT_, B_), 128>>>(memory, out_w);
    context_reduce_kernel<<<B_, 128>>>(out);
}

// round 6
// speedup vs baseline: 1.2738x; 1.1156x over previous
#include <cuda_runtime.h>
#include <cuda_bf16.h>
#include <cstdint>

#define B_    128
#define T_    1024
#define RNN_  1024
#define EMB_  512
#define ATT_  128
#define NF_   32
#define KS_   31
#define PAD_  15
#define CTILE_ 64
#define CNT_   (T_ / CTILE_)   // 16

// energies GEMM per 128-t tile: D[128,128] = A[t,192] * B[192,a]
// segments: s0-3: Ahi*Bhi, s4-7: Alo*Bhi(dup), s8-11: Ahi*Blo
#define LDAB_  136                              // bf16 elems per smem row (272 B)
#define OFF_B_    (128 * LDAB_ * 2)             // 34816
#define OFF_AWR_  (OFF_B_ + 192 * LDAB_ * 2)    // 87040: aw rows 2 x 1056 f
#define OFF_V_    (OFF_AWR_ + 8448)             // 95488
#define OFF_E_    (OFF_V_ + 512)                // 96000: energies 1024 f
#define OFF_RED_  (OFF_E_ + 4096)               // 100096
#define ESMEM_    (OFF_RED_ + 256)              // 100352

// ---------------- scratch (no allocations allowed) ----------------
__device__ float g_pq[B_ * ATT_];
__device__ float g_partial[B_ * CNT_ * EMB_];
__device__ __nv_bfloat16 g_W2bf[192 * 128];   // B rows: [hi | hi dup | lo]

// ---------------- helpers ----------------
__device__ __forceinline__ float tanh_fast(float x) {
    float y; asm("tanh.approx.f32 %0, %1;" : "=f"(y) : "f"(x)); return y;
}
__device__ __forceinline__ uint32_t smem_u32(const void* p) {
    uint32_t a;
    asm("{ .reg .u64 t; cvta.to.shared.u64 t, %1; cvt.u32.u64 %0, t; }" : "=r"(a) : "l"(p));
    return a;
}
__device__ __forceinline__ void ldsm_x4(uint32_t* r, uint32_t addr) {
    asm volatile("ldmatrix.sync.aligned.m8n8.x4.shared.b16 {%0,%1,%2,%3}, [%4];"
                 : "=r"(r[0]), "=r"(r[1]), "=r"(r[2]), "=r"(r[3]) : "r"(addr));
}
__device__ __forceinline__ void ldsm_x2t(uint32_t& b0, uint32_t& b1, uint32_t addr) {
    asm volatile("ldmatrix.sync.aligned.m8n8.x2.trans.shared.b16 {%0,%1}, [%2];"
                 : "=r"(b0), "=r"(b1) : "r"(addr));
}
__device__ __forceinline__ void mma_bf16(float* d, const uint32_t* a, uint32_t b0, uint32_t b1) {
    asm volatile("mma.sync.aligned.m16n8k16.row.col.f32.bf16.bf16.f32 "
                 "{%0,%1,%2,%3}, {%4,%5,%6,%7}, {%8,%9}, {%0,%1,%2,%3};"
                 : "+f"(d[0]), "+f"(d[1]), "+f"(d[2]), "+f"(d[3])
                 : "r"(a[0]), "r"(a[1]), "r"(a[2]), "r"(a[3]), "r"(b0), "r"(b1));
}

// ================= K1: prep — pq tiles (blocks 0..63) + W2 build (block 64) =================
__global__ __launch_bounds__(256) void prep_kernel(
    const float* __restrict__ hidden, const float* __restrict__ wq,
    const float* __restrict__ wconv,  const float* __restrict__ wloc)
{
    __shared__ float s_buf[8192];
    const int tid = threadIdx.x;

    if (blockIdx.x < 64) {
        const int b0 = (blockIdx.x >> 3) * 16;
        const int a0 = (blockIdx.x & 7) * 16;
        float* sH = s_buf;              // [16][129]
        float* sW = s_buf + 16 * 129;   // [128][17]
        const int bb = tid >> 4, ag = tid & 15;
        float acc0 = 0.f, acc1 = 0.f;
        for (int kc = 0; kc < RNN_; kc += 128) {
            __syncthreads();
            #pragma unroll
            for (int i = 0; i < 8; ++i) {
                int m = tid + 256 * i, r = m >> 7, c = m & 127;
                sH[r * 129 + c] = hidden[(size_t)(b0 + r) * RNN_ + kc + c];
            }
            #pragma unroll
            for (int i = 0; i < 8; ++i) {
                int m = tid + 256 * i, r = m >> 4, c = m & 15;
                sW[r * 17 + c] = wq[(size_t)(kc + r) * ATT_ + a0 + c];
            }
            __syncthreads();
            #pragma unroll
            for (int k = 0; k < 128; k += 2) {
                acc0 = fmaf(sH[bb * 129 + k],     sW[k * 17 + ag],       acc0);
                acc1 = fmaf(sH[bb * 129 + k + 1], sW[(k + 1) * 17 + ag], acc1);
            }
        }
        g_pq[(b0 + bb) * ATT_ + a0 + ag] = acc0 + acc1;
    } else {
        // W2[j,a] = sum_f wconv[f*62+j] * wloc[f*128+a], j in [0,62)
        float* s_W2 = s_buf;
        for (int m = tid; m < 62 * 128; m += 256) {
            int j = m >> 7, a = m & 127;
            float acc = 0.f;
            #pragma unroll 8
            for (int f = 0; f < NF_; ++f)
                acc = fmaf(wconv[f * 62 + j], wloc[f * ATT_ + a], acc);
            s_W2[m] = acc;
        }
        __syncthreads();
        for (int m = tid; m < 192 * 128; m += 256) {
            int row = m >> 7, a = m & 127;
            int seg = row >> 6, j = row & 63;
            __nv_bfloat16 out = __float2bfloat16_rn(0.f);
            if (j < 62) {
                float w = s_W2[j * 128 + a];
                __nv_bfloat16 hi = __float2bfloat16_rn(w);
                out = (seg < 2) ? hi : __float2bfloat16_rn(w - __bfloat162float(hi));
            }
            g_W2bf[m] = out;
        }
    }
}

// ============ K2: energies (MMA over 8 t-tiles) + fused softmax, 1 block / b ============
__global__ __launch_bounds__(256, 1) void energies_softmax_kernel(
    const float* __restrict__ aw,      // [B,2,T]
    const float* __restrict__ pmem,    // [B,T,ATT]
    const float* __restrict__ vvec,    // [ATT]
    const unsigned char* __restrict__ mask,
    float* __restrict__ out_w)
{
    extern __shared__ __align__(16) char sm[];
    const uint32_t sbase = smem_u32(sm);

    const int b   = blockIdx.x;
    const int tid = threadIdx.x;
    const int wm  = tid >> 5, lane = tid & 31;

    float* s_awr = (float*)(sm + OFF_AWR_);   // [2][1056], s_awr[ch][i] = aw[gt = i-16]
    float* s_v   = (float*)(sm + OFF_V_);
    float* s_e   = (float*)(sm + OFF_E_);
    float* s_red = (float*)(sm + OFF_RED_);

    // ---- one-time staging ----
    {
        const uint32_t* gw = (const uint32_t*)g_W2bf;   // [192][64] u32
        for (int m = tid; m < 192 * 64; m += 256) {
            int r = m >> 6, c = m & 63;
            *(uint32_t*)(sm + OFF_B_ + r * (LDAB_ * 2) + c * 4) = gw[m];
        }
    }
    for (int idx = tid; idx < 2112; idx += 256) {
        int ch = idx >> 10 >> 1;                       // idx/2112 half split below
        ch = idx / 1056; int i = idx - ch * 1056;
        int gt = i - 16;
        s_awr[idx] = (gt >= 0 && gt < T_) ? aw[((size_t)b * 2 + ch) * T_ + gt] : 0.f;
    }
    if (tid < 128) {
        s_v[tid] = vvec[tid];
        // pq rows in B
        float q = g_pq[b * ATT_ + tid];
        __nv_bfloat16 hi = __float2bfloat16_rn(q);
        __nv_bfloat16 lo = __float2bfloat16_rn(q - __bfloat162float(hi));
        __nv_bfloat16* sB = (__nv_bfloat16*)(sm + OFF_B_);
        sB[ 62 * LDAB_ + tid] = hi;
        sB[126 * LDAB_ + tid] = hi;
        sB[190 * LDAB_ + tid] = lo;
        // constant A columns (same every tile): row tid
        __nv_bfloat16* arow = (__nv_bfloat16*)(sm + tid * (LDAB_ * 2));
        arow[62]  = __float2bfloat16_rn(1.f);
        arow[63]  = __float2bfloat16_rn(0.f);
        arow[126] = __float2bfloat16_rn(0.f);
        arow[127] = __float2bfloat16_rn(0.f);
    }
    __syncthreads();

    // ---- per-warp constants ----
    const uint32_t aRowAddr = sbase + (16 * wm + (lane & 15)) * (LDAB_ * 2) + (lane >> 4) * 16;
    const uint32_t bRowAddr = sbase + OFF_B_ + (lane & 15) * (LDAB_ * 2);
    const int rowL = tid >> 1;               // A row this thread builds (warp-local set)
    const int jh   = tid & 1;

    // ---- 8 t-tiles, no block syncs (A rows warp-private, B immutable) ----
    for (int it = 0; it < 8; ++it) {
        const int t0g = it * 128;

        // build A row (cols 0..61 hi, 64..125 lo)
        {
            __nv_bfloat16* arow = (__nv_bfloat16*)(sm + rowL * (LDAB_ * 2));
            const int base0 = 1 + t0g + rowL;          // s_awr idx for ch0, j offset
            #pragma unroll
            for (int q = 0; q < 31; ++q) {
                int j = jh * 31 + q;
                float x = (j < 31) ? s_awr[base0 + j] : s_awr[1056 + base0 + (j - 31)];
                __nv_bfloat16 hi = __float2bfloat16_rn(x);
                arow[j]      = hi;
                arow[64 + j] = __float2bfloat16_rn(x - __bfloat162float(hi));
            }
        }
        __syncwarp();

        // MMA: 12 k-steps x 16 n-tiles
        float acc[16][4];
        #pragma unroll
        for (int n = 0; n < 16; ++n) {
            acc[n][0] = 0.f; acc[n][1] = 0.f; acc[n][2] = 0.f; acc[n][3] = 0.f;
        }
        #pragma unroll
        for (int s = 0; s < 12; ++s) {
            const int ks = (s < 8) ? s : (s - 8);
            uint32_t af[4];
            ldsm_x4(af, aRowAddr + ks * 32);
            const uint32_t bS = bRowAddr + s * 16 * (LDAB_ * 2);
            #pragma unroll
            for (int n = 0; n < 16; ++n) {
                uint32_t b0, b1;
                ldsm_x2t(b0, b1, bS + n * 16);
                mma_bf16(acc[n], af, b0, b1);
            }
        }
        __syncwarp();

        // epilogue -> s_e
        {
            const int r  = lane >> 2;
            const int cq = (lane & 3) * 2;
            const int tA = t0g + 16 * wm + r;
            const float* pmA = pmem + ((size_t)b * T_ + tA) * ATT_;
            const float* pmB = pmA + 8 * ATT_;
            float eA = 0.f, eB = 0.f;
            #pragma unroll
            for (int n = 0; n < 16; ++n) {
                const int col = 8 * n + cq;
                float2 v2 = *(const float2*)(s_v + col);
                float2 pa = *(const float2*)(pmA + col);
                float2 pb = *(const float2*)(pmB + col);
                eA = fmaf(tanh_fast(acc[n][0] + pa.x), v2.x, eA);
                eA = fmaf(tanh_fast(acc[n][1] + pa.y), v2.y, eA);
                eB = fmaf(tanh_fast(acc[n][2] + pb.x), v2.x, eB);
                eB = fmaf(tanh_fast(acc[n][3] + pb.y), v2.y, eB);
            }
            eA += __shfl_xor_sync(0xffffffffu, eA, 1);
            eA += __shfl_xor_sync(0xffffffffu, eA, 2);
            eB += __shfl_xor_sync(0xffffffffu, eB, 1);
            eB += __shfl_xor_sync(0xffffffffu, eB, 2);
            if ((lane & 3) == 0) {
                s_e[tA]     = eA;
                s_e[tA + 8] = eB;
            }
        }
    }
    __syncthreads();

    // ---- fused softmax over the 1024 energies ----
    {
        float4 ev = ((const float4*)s_e)[tid];
        const uchar4 mk = ((const uchar4*)(mask + (size_t)b * T_))[tid];
        const float NINF = -__int_as_float(0x7f800000);
        if (mk.x) ev.x = NINF;
        if (mk.y) ev.y = NINF;
        if (mk.z) ev.z = NINF;
        if (mk.w) ev.w = NINF;

        float m = fmaxf(fmaxf(ev.x, ev.y), fmaxf(ev.z, ev.w));
        #pragma unroll
        for (int o = 16; o; o >>= 1) m = fmaxf(m, __shfl_xor_sync(0xffffffffu, m, o));
        if (lane == 0) s_red[wm] = m;
        __syncthreads();
        if (wm == 0) {
            float mm = (lane < 8) ? s_red[lane] : NINF;
            #pragma unroll
            for (int o = 4; o; o >>= 1) mm = fmaxf(mm, __shfl_xor_sync(0xffffffffu, mm, o));
            if (lane == 0) s_red[8] = mm;
        }
        __syncthreads();
        m = s_red[8];

        float4 p;
        p.x = expf(ev.x - m); p.y = expf(ev.y - m);
        p.z = expf(ev.z - m); p.w = expf(ev.w - m);
        float s = (p.x + p.y) + (p.z + p.w);
        #pragma unroll
        for (int o = 16; o; o >>= 1) s += __shfl_xor_sync(0xffffffffu, s, o);
        if (lane == 0) s_red[16 + wm] = s;
        __syncthreads();
        if (wm == 0) {
            float ss = (lane < 8) ? s_red[16 + lane] : 0.f;
            #pragma unroll
            for (int o = 4; o; o >>= 1) ss += __shfl_xor_sync(0xffffffffu, ss, o);
            if (lane == 0) s_red[24] = ss;
        }
        __syncthreads();
        const float inv = 1.f / s_red[24];

        p.x *= inv; p.y *= inv; p.z *= inv; p.w *= inv;
        ((float4*)(out_w + (size_t)b * T_))[tid] = p;
    }
}

// ============ K3: context partials: grid (CNT_, B_), 128 thr ============
__global__ __launch_bounds__(128) void context_partial_kernel(
    const float* __restrict__ memory,
    const float* __restrict__ out_w)
{
    const int c = blockIdx.x, b = blockIdx.y, d4 = threadIdx.x;
    __shared__ float s_w[CTILE_];
    if (threadIdx.x < CTILE_)
        s_w[threadIdx.x] = out_w[(size_t)b * T_ + c * CTILE_ + threadIdx.x];
    __syncthreads();

    const float4* mem4 = (const float4*)memory + ((size_t)b * T_ + c * CTILE_) * (EMB_ / 4) + d4;
    float4 acc = make_float4(0.f, 0.f, 0.f, 0.f);
    #pragma unroll 8
    for (int j = 0; j < CTILE_; ++j) {
        float wt = s_w[j];
        float4 mv = __ldcs(mem4 + (size_t)j * (EMB_ / 4));
        acc.x = fmaf(wt, mv.x, acc.x);
        acc.y = fmaf(wt, mv.y, acc.y);
        acc.z = fmaf(wt, mv.z, acc.z);
        acc.w = fmaf(wt, mv.w, acc.w);
    }
    ((float4*)g_partial)[((size_t)b * CNT_ + c) * (EMB_ / 4) + d4] = acc;
}

// ================= K4: reduce partials -> context =================
__global__ __launch_bounds__(128) void context_reduce_kernel(float* __restrict__ out) {
    const int b = blockIdx.x, d4 = threadIdx.x;
    const float4* p4 = (const float4*)g_partial;
    float4 s = make_float4(0.f, 0.f, 0.f, 0.f);
    #pragma unroll
    for (int c = 0; c < CNT_; ++c) {
        float4 v = p4[((size_t)b * CNT_ + c) * (EMB_ / 4) + d4];
        s.x += v.x; s.y += v.y; s.z += v.z; s.w += v.w;
    }
    ((float4*)out)[(size_t)b * (EMB_ / 4) + d4] = s;
}

// ============================ launch ============================
extern "C" void kernel_launch(void* const* d_in, const int* in_sizes, int n_in,
                              void* d_out, int out_size) {
    const float* hidden = (const float*)d_in[0];
    const float* memory = (const float*)d_in[1];
    const float* pmem   = (const float*)d_in[2];
    const float* awcat  = (const float*)d_in[3];
    const unsigned char* mask = (const unsigned char*)d_in[4];
    const float* wq     = (const float*)d_in[5];
    const float* wconv  = (const float*)d_in[6];
    const float* wloc   = (const float*)d_in[7];
    const float* vvec   = (const float*)d_in[8];

    float* out   = (float*)d_out;
    float* out_w = out + (size_t)B_ * EMB_;

    cudaFuncSetAttribute(energies_softmax_kernel,
                         cudaFuncAttributeMaxDynamicSharedMemorySize, ESMEM_);

    prep_kernel<<<65, 256>>>(hidden, wq, wconv, wloc);
    energies_softmax_kernel<<<B_, 256, ESMEM_>>>(awcat, pmem, vvec, mask, out_w);
    context_partial_kernel<<<dim3(CNT_, B_), 128>>>(memory, out_w);
    context_reduce_kernel<<<B_, 128>>>(out);
}

// round 7
// speedup vs baseline: 1.3646x; 1.0713x over previous
#include <cuda_runtime.h>
#include <cuda_bf16.h>
#include <cstdint>

#define B_    128
#define T_    1024
#define RNN_  1024
#define EMB_  512
#define ATT_  128
#define NF_   32
#define KS_   31
#define PAD_  15

// energies GEMM per 128-t tile: D[128,128] = A[t,192] * B[192,a], B dedup to 128 rows
// s0-3: Ahi x Bhi, s4-7: Alo x Bhi, s8-11: Ahi x Blo
#define LDAB_  136                              // bf16 elems per smem row (272 B)
#define OFF_B_    (128 * LDAB_ * 2)             // 34816
#define OFF_AWR_  (OFF_B_ + 128 * LDAB_ * 2)    // 69632: aw rows 2 x 1056 f
#define OFF_V_    (OFF_AWR_ + 8448)             // 78080
#define OFF_E_    (OFF_V_ + 512)                // 78592: energies 2 x 1024 f
#define OFF_RED_  (OFF_E_ + 8192)               // 86784
#define ESMEM_    (OFF_RED_ + 256)              // 87040

// ---------------- scratch (no allocations allowed) ----------------
__device__ float g_pq[B_ * ATT_];
__device__ __nv_bfloat16 g_W2bf[128 * 128];   // rows 0..63 hi, 64..127 lo (j>=62 zero)

// ---------------- helpers ----------------
__device__ __forceinline__ float tanh_fast(float x) {
    float y; asm("tanh.approx.f32 %0, %1;" : "=f"(y) : "f"(x)); return y;
}
__device__ __forceinline__ uint32_t smem_u32(const void* p) {
    uint32_t a;
    asm("{ .reg .u64 t; cvta.to.shared.u64 t, %1; cvt.u32.u64 %0, t; }" : "=r"(a) : "l"(p));
    return a;
}
__device__ __forceinline__ void ldsm_x4(uint32_t* r, uint32_t addr) {
    asm volatile("ldmatrix.sync.aligned.m8n8.x4.shared.b16 {%0,%1,%2,%3}, [%4];"
                 : "=r"(r[0]), "=r"(r[1]), "=r"(r[2]), "=r"(r[3]) : "r"(addr));
}
__device__ __forceinline__ void ldsm_x2t(uint32_t& b0, uint32_t& b1, uint32_t addr) {
    asm volatile("ldmatrix.sync.aligned.m8n8.x2.trans.shared.b16 {%0,%1}, [%2];"
                 : "=r"(b0), "=r"(b1) : "r"(addr));
}
__device__ __forceinline__ void mma_bf16(float* d, const uint32_t* a, uint32_t b0, uint32_t b1) {
    asm volatile("mma.sync.aligned.m16n8k16.row.col.f32.bf16.bf16.f32 "
                 "{%0,%1,%2,%3}, {%4,%5,%6,%7}, {%8,%9}, {%0,%1,%2,%3};"
                 : "+f"(d[0]), "+f"(d[1]), "+f"(d[2]), "+f"(d[3])
                 : "r"(a[0]), "r"(a[1]), "r"(a[2]), "r"(a[3]), "r"(b0), "r"(b1));
}

// ================= K1: prep — pq tiles (blocks 0..63) + W2 build (block 64) =================
__global__ __launch_bounds__(256) void prep_kernel(
    const float* __restrict__ hidden, const float* __restrict__ wq,
    const float* __restrict__ wconv,  const float* __restrict__ wloc)
{
    __shared__ float s_buf[8192];
    const int tid = threadIdx.x;

    if (blockIdx.x < 64) {
        const int b0 = (blockIdx.x >> 3) * 16;
        const int a0 = (blockIdx.x & 7) * 16;
        float* sH = s_buf;              // [16][129]
        float* sW = s_buf + 16 * 129;   // [128][17]
        const int bb = tid >> 4, ag = tid & 15;
        float acc0 = 0.f, acc1 = 0.f;
        for (int kc = 0; kc < RNN_; kc += 128) {
            __syncthreads();
            #pragma unroll
            for (int i = 0; i < 8; ++i) {
                int m = tid + 256 * i, r = m >> 7, c = m & 127;
                sH[r * 129 + c] = hidden[(size_t)(b0 + r) * RNN_ + kc + c];
            }
            #pragma unroll
            for (int i = 0; i < 8; ++i) {
                int m = tid + 256 * i, r = m >> 4, c = m & 15;
                sW[r * 17 + c] = wq[(size_t)(kc + r) * ATT_ + a0 + c];
            }
            __syncthreads();
            #pragma unroll
            for (int k = 0; k < 128; k += 2) {
                acc0 = fmaf(sH[bb * 129 + k],     sW[k * 17 + ag],       acc0);
                acc1 = fmaf(sH[bb * 129 + k + 1], sW[(k + 1) * 17 + ag], acc1);
            }
        }
        g_pq[(b0 + bb) * ATT_ + a0 + ag] = acc0 + acc1;
    } else {
        // W2[j,a] = sum_f wconv[f*62+j] * wloc[f*128+a], j in [0,62)
        float* s_W2 = s_buf;
        for (int m = tid; m < 62 * 128; m += 256) {
            int j = m >> 7, a = m & 127;
            float acc = 0.f;
            #pragma unroll 8
            for (int f = 0; f < NF_; ++f)
                acc = fmaf(wconv[f * 62 + j], wloc[f * ATT_ + a], acc);
            s_W2[m] = acc;
        }
        __syncthreads();
        for (int m = tid; m < 128 * 128; m += 256) {
            int row = m >> 7, a = m & 127;
            int seg = row >> 6, j = row & 63;
            __nv_bfloat16 out = __float2bfloat16_rn(0.f);
            if (j < 62) {
                float w = s_W2[j * 128 + a];
                __nv_bfloat16 hi = __float2bfloat16_rn(w);
                out = (seg == 0) ? hi : __float2bfloat16_rn(w - __bfloat162float(hi));
            }
            g_W2bf[m] = out;
        }
    }
}

// ============ K2: energies (MMA over 8 t-tiles, 16 warps) + fused softmax, 1 block/b ============
__global__ __launch_bounds__(512, 1) void energies_softmax_kernel(
    const float* __restrict__ aw,      // [B,2,T]
    const float* __restrict__ pmem,    // [B,T,ATT]
    const float* __restrict__ vvec,    // [ATT]
    const unsigned char* __restrict__ mask,
    float* __restrict__ out_w)
{
    extern __shared__ __align__(16) char sm[];
    const uint32_t sbase = smem_u32(sm);

    const int b    = blockIdx.x;
    const int tid  = threadIdx.x;
    const int wm   = tid >> 5, lane = tid & 31;
    const int slab = wm >> 1;          // 0..7: t rows [16*slab, 16*slab+16)
    const int nh   = wm & 1;           // 0..1: n-tiles [8*nh, 8*nh+8)

    float* s_awr = (float*)(sm + OFF_AWR_);   // [2][1056], s_awr[ch][i] = aw[gt=i-16]
    float* s_v   = (float*)(sm + OFF_V_);
    float* s_e   = (float*)(sm + OFF_E_);     // [2][1024] per-nh partials
    float* s_red = (float*)(sm + OFF_RED_);

    // ---- one-time staging ----
    {
        const uint32_t* gw = (const uint32_t*)g_W2bf;   // [128][64] u32
        for (int m = tid; m < 128 * 64; m += 512) {
            int r = m >> 6, c = m & 63;
            *(uint32_t*)(sm + OFF_B_ + r * (LDAB_ * 2) + c * 4) = gw[m];
        }
    }
    for (int idx = tid; idx < 2112; idx += 512) {
        int ch = idx / 1056, i = idx - ch * 1056;
        int gt = i - 16;
        s_awr[idx] = (gt >= 0 && gt < T_) ? aw[((size_t)b * 2 + ch) * T_ + gt] : 0.f;
    }
    if (tid < 128) {
        s_v[tid] = vvec[tid];
        // pq rows in B: hi at row 62, lo at row 126
        float q = g_pq[b * ATT_ + tid];
        __nv_bfloat16 hi = __float2bfloat16_rn(q);
        __nv_bfloat16 lo = __float2bfloat16_rn(q - __bfloat162float(hi));
        __nv_bfloat16* sB = (__nv_bfloat16*)(sm + OFF_B_);
        sB[ 62 * LDAB_ + tid] = hi;
        sB[126 * LDAB_ + tid] = lo;
        // constant A columns: hi col 62 = 1.0, 63 = 0; lo cols 126,127 = 0
        __nv_bfloat16* arow = (__nv_bfloat16*)(sm + tid * (LDAB_ * 2));
        arow[62]  = __float2bfloat16_rn(1.f);
        arow[63]  = __float2bfloat16_rn(0.f);
        arow[126] = __float2bfloat16_rn(0.f);
        arow[127] = __float2bfloat16_rn(0.f);
    }

    const uint32_t aRowAddr = sbase + (16 * slab + (lane & 15)) * (LDAB_ * 2) + (lane >> 4) * 16;
    const uint32_t bRowAddr = sbase + OFF_B_ + (lane & 15) * (LDAB_ * 2) + nh * 128;
    const int rowL = tid >> 2;            // A row this thread builds
    const int jq   = tid & 3;             // 16-col group within the row

    // ---- 8 t-tiles ----
    for (int it = 0; it < 8; ++it) {
        const int t0g = it * 128;

        __syncthreads();   // prior tile's ldsm reads of A are done
        {
            __nv_bfloat16* arow = (__nv_bfloat16*)(sm + rowL * (LDAB_ * 2));
            const int base0 = 1 + t0g + rowL;
            #pragma unroll
            for (int q = 0; q < 16; ++q) {
                int j = jq * 16 + q;
                if (j < 62) {
                    float x = (j < 31) ? s_awr[base0 + j] : s_awr[1056 + base0 + (j - 31)];
                    __nv_bfloat16 hi = __float2bfloat16_rn(x);
                    arow[j]      = hi;
                    arow[64 + j] = __float2bfloat16_rn(x - __bfloat162float(hi));
                }
            }
        }
        __syncthreads();   // A tile visible to all warps

        // MMA: 12 k-steps x 8 n-tiles per warp
        float acc[8][4];
        #pragma unroll
        for (int n = 0; n < 8; ++n) {
            acc[n][0] = 0.f; acc[n][1] = 0.f; acc[n][2] = 0.f; acc[n][3] = 0.f;
        }
        #pragma unroll
        for (int s = 0; s < 12; ++s) {
            const int ksa = (s < 8) ? s : (s - 8);
            const int ksb = (s < 4) ? s : (s - 4);
            uint32_t af[4];
            ldsm_x4(af, aRowAddr + ksa * 32);
            const uint32_t bS = bRowAddr + ksb * 16 * (LDAB_ * 2);
            #pragma unroll
            for (int n = 0; n < 8; ++n) {
                uint32_t b0, b1;
                ldsm_x2t(b0, b1, bS + n * 16);
                mma_bf16(acc[n], af, b0, b1);
            }
        }

        // epilogue -> s_e[nh]
        {
            const int r  = lane >> 2;
            const int cq = (lane & 3) * 2;
            const int tA = t0g + 16 * slab + r;
            const float* pmA = pmem + ((size_t)b * T_ + tA) * ATT_;
            const float* pmB = pmA + 8 * ATT_;
            float eA = 0.f, eB = 0.f;
            #pragma unroll
            for (int n = 0; n < 8; ++n) {
                const int col = 64 * nh + 8 * n + cq;
                float2 v2 = *(const float2*)(s_v + col);
                float2 pa = *(const float2*)(pmA + col);
                float2 pb = *(const float2*)(pmB + col);
                eA = fmaf(tanh_fast(acc[n][0] + pa.x), v2.x, eA);
                eA = fmaf(tanh_fast(acc[n][1] + pa.y), v2.y, eA);
                eB = fmaf(tanh_fast(acc[n][2] + pb.x), v2.x, eB);
                eB = fmaf(tanh_fast(acc[n][3] + pb.y), v2.y, eB);
            }
            eA += __shfl_xor_sync(0xffffffffu, eA, 1);
            eA += __shfl_xor_sync(0xffffffffu, eA, 2);
            eB += __shfl_xor_sync(0xffffffffu, eB, 1);
            eB += __shfl_xor_sync(0xffffffffu, eB, 2);
            if ((lane & 3) == 0) {
                s_e[nh * 1024 + tA]     = eA;
                s_e[nh * 1024 + tA + 8] = eB;
            }
        }
    }
    __syncthreads();

    // ---- fused softmax over 1024 energies (512 threads, 2 each) ----
    {
        float2 e0 = ((const float2*)s_e)[tid];
        float2 e1 = ((const float2*)(s_e + 1024))[tid];
        float2 ev; ev.x = e0.x + e1.x; ev.y = e0.y + e1.y;
        const uchar2 mk = ((const uchar2*)(mask + (size_t)b * T_))[tid];
        const float NINF = -__int_as_float(0x7f800000);
        if (mk.x) ev.x = NINF;
        if (mk.y) ev.y = NINF;

        float m = fmaxf(ev.x, ev.y);
        #pragma unroll
        for (int o = 16; o; o >>= 1) m = fmaxf(m, __shfl_xor_sync(0xffffffffu, m, o));
        if (lane == 0) s_red[wm] = m;
        __syncthreads();
        if (wm == 0) {
            float mm = (lane < 16) ? s_red[lane] : NINF;
            #pragma unroll
            for (int o = 8; o; o >>= 1) mm = fmaxf(mm, __shfl_xor_sync(0xffffffffu, mm, o));
            if (lane == 0) s_red[16] = mm;
        }
        __syncthreads();
        m = s_red[16];

        float2 p;
        p.x = expf(ev.x - m); p.y = expf(ev.y - m);
        float s = p.x + p.y;
        #pragma unroll
        for (int o = 16; o; o >>= 1) s += __shfl_xor_sync(0xffffffffu, s, o);
        if (lane == 0) s_red[32 + wm] = s;
        __syncthreads();
        if (wm == 0) {
            float ss = (lane < 16) ? s_red[32 + lane] : 0.f;
            #pragma unroll
            for (int o = 8; o; o >>= 1) ss += __shfl_xor_sync(0xffffffffu, ss, o);
            if (lane == 0) s_red[48] = ss;
        }
        __syncthreads();
        const float inv = 1.f / s_red[48];

        p.x *= inv; p.y *= inv;
        ((float2*)(out_w + (size_t)b * T_))[tid] = p;
    }
}

// ============ K3: context, single pass: grid (4, B_), 256 thr ============
__global__ __launch_bounds__(256) void context_kernel(
    const float* __restrict__ memory,   // [B,T,EMB]
    const float* __restrict__ out_w,    // weights [B,T]
    float* __restrict__ out)            // context [B,EMB]
{
    const int ec = blockIdx.x, b = blockIdx.y;
    const int tid = threadIdx.x;
    const int g = tid >> 5, l = tid & 31;   // g: t-phase, l: float4 lane

    __shared__ float s_w[T_];
    __shared__ float4 s_acc[256];

    #pragma unroll
    for (int i = 0; i < 4; ++i)
        s_w[tid + 256 * i] = out_w[(size_t)b * T_ + tid + 256 * i];
    __syncthreads();

    const float4* mem4 = (const float4*)memory + ((size_t)b * T_) * (EMB_ / 4) + ec * 32 + l;
    float4 acc = make_float4(0.f, 0.f, 0.f, 0.f);
    #pragma unroll 4
    for (int t = g; t < T_; t += 8) {
        float wt = s_w[t];
        float4 mv = __ldcs(mem4 + (size_t)t * (EMB_ / 4));
        acc.x = fmaf(wt, mv.x, acc.x);
        acc.y = fmaf(wt, mv.y, acc.y);
        acc.z = fmaf(wt, mv.z, acc.z);
        acc.w = fmaf(wt, mv.w, acc.w);
    }
    s_acc[tid] = acc;
    __syncthreads();
    if (g < 4) {
        float4 o = s_acc[tid + 128];
        acc.x += o.x; acc.y += o.y; acc.z += o.z; acc.w += o.w;
        s_acc[tid] = acc;
    }
    __syncthreads();
    if (g < 2) {
        float4 o = s_acc[tid + 64];
        acc.x += o.x; acc.y += o.y; acc.z += o.z; acc.w += o.w;
        s_acc[tid] = acc;
    }
    __syncthreads();
    if (g == 0) {
        float4 o = s_acc[tid + 32];
        acc.x += o.x; acc.y += o.y; acc.z += o.z; acc.w += o.w;
        ((float4*)out)[(size_t)b * (EMB_ / 4) + ec * 32 + l] = acc;
    }
}

// ============================ launch ============================
extern "C" void kernel_launch(void* const* d_in, const int* in_sizes, int n_in,
                              void* d_out, int out_size) {
    const float* hidden = (const float*)d_in[0];
    const float* memory = (const float*)d_in[1];
    const float* pmem   = (const float*)d_in[2];
    const float* awcat  = (const float*)d_in[3];
    const unsigned char* mask = (const unsigned char*)d_in[4];
    const float* wq     = (const float*)d_in[5];
    const float* wconv  = (const float*)d_in[6];
    const float* wloc   = (const float*)d_in[7];
    const float* vvec   = (const float*)d_in[8];

    float* out   = (float*)d_out;
    float* out_w = out + (size_t)B_ * EMB_;

    cudaFuncSetAttribute(energies_softmax_kernel,
                         cudaFuncAttributeMaxDynamicSharedMemorySize, ESMEM_);

    prep_kernel<<<65, 256>>>(hidden, wq, wconv, wloc);
    energies_softmax_kernel<<<B_, 512, ESMEM_>>>(awcat, pmem, vvec, mask, out_w);
    context_kernel<<<dim3(4, B_), 256>>>(memory, out_w, out);
}